// round 2
// baseline (speedup 1.0000x reference)
#include <cuda_runtime.h>

#define F 16384
#define NJ 22
#define STRIDE (NJ*3)   // 66 floats per frame
#define NBINS 25
#define INV4PI 0.07957747154594767f

// ---------------- device scratch (no allocs allowed) ----------------
__device__ float g_m1T[STRIDE * F];   // [j*3+c][frame]
__device__ float g_m2T[STRIDE * F];
__device__ unsigned char g_flag[F];
__device__ float g_gli[NBINS * F];    // [bin][frame]

__constant__ int c_pathj[5][5] = {
    {2, 5, 8, 11, 0},
    {1, 4, 7, 10, 0},
    {3, 6, 9, 12, 15},
    {14, 17, 19, 21, 0},
    {13, 16, 18, 20, 0}
};
__constant__ int c_plen[5] = {4, 4, 5, 4, 4};

// ---------------- small vec helpers ----------------
struct V3 { float x, y, z; };

__device__ __forceinline__ V3 vsub(V3 a, V3 b) { return {a.x - b.x, a.y - b.y, a.z - b.z}; }
__device__ __forceinline__ V3 vcrs(V3 a, V3 b) {
    return {fmaf(a.y, b.z, -a.z * b.y),
            fmaf(a.z, b.x, -a.x * b.z),
            fmaf(a.x, b.y, -a.y * b.x)};
}
__device__ __forceinline__ float vdot(V3 a, V3 b) {
    return fmaf(a.x, b.x, fmaf(a.y, b.y, a.z * b.z));
}
// _safe_normalize semantics: zero vector -> zero (so downstream dot -> 0)
__device__ __forceinline__ float invnorm(V3 v) {
    float n2 = vdot(v, v);
    return (n2 > 0.f) ? rsqrtf(n2) : 0.f;
}
__device__ __forceinline__ float edge_asin(V3 a, float ra, V3 b, float rb) {
    float d = vdot(a, b) * ra * rb;
    d = fminf(1.f, fmaxf(-1.f, d));
    return asinf(d);
}

// ---------------- kernel 1: AoS->SoA transpose ----------------
__global__ void transpose_kernel(const float* __restrict__ m1,
                                 const float* __restrict__ m2) {
    __shared__ float tile[32 * STRIDE];
    int f0 = blockIdx.x * 32;
    const float* in = blockIdx.y ? m2 : m1;
    float* out = blockIdx.y ? g_m2T : g_m1T;

    // coalesced read of 32 contiguous frames (32*66 floats)
    for (int idx = threadIdx.x; idx < 32 * STRIDE; idx += blockDim.x)
        tile[idx] = in[f0 * STRIDE + idx];
    __syncthreads();
    // coalesced write: 32 consecutive frames per slot
    for (int idx = threadIdx.x; idx < 32 * STRIDE; idx += blockDim.x) {
        int slot = idx >> 5;
        int lane = idx & 31;
        out[slot * F + f0 + lane] = tile[lane * STRIDE + slot];
    }
}

// ---------------- kernel 2: per-frame XZ bbox overlap flag ----------------
__global__ void mask_kernel() {
    int f = blockIdx.x * blockDim.x + threadIdx.x;
    if (f >= F) return;
    float x1n = 1e30f, x1x = -1e30f, z1n = 1e30f, z1x = -1e30f;
    float x2n = 1e30f, x2x = -1e30f, z2n = 1e30f, z2x = -1e30f;
#pragma unroll
    for (int j = 0; j < NJ; j++) {
        float x1 = g_m1T[(j * 3 + 0) * F + f];
        float z1 = g_m1T[(j * 3 + 2) * F + f];
        float x2 = g_m2T[(j * 3 + 0) * F + f];
        float z2 = g_m2T[(j * 3 + 2) * F + f];
        x1n = fminf(x1n, x1); x1x = fmaxf(x1x, x1);
        z1n = fminf(z1n, z1); z1x = fmaxf(z1x, z1);
        x2n = fminf(x2n, x2); x2x = fmaxf(x2x, x2);
        z2n = fminf(z2n, z2); z2x = fmaxf(z2x, z2);
    }
    bool ovx = !((x1x < x2n) || (x2x < x1n));
    bool ovz = !((z1x < z2n) || (z2x < z1n));
    g_flag[f] = (unsigned char)(ovx && ovz);
}

// ---------------- GLI pair sum (fully unrolled via templates) ----------------
template <int NA, int NB>
__device__ __forceinline__ float gli_body(int f, int a, int b) {
    V3 P1[NA], P2[NB];
#pragma unroll
    for (int k = 0; k < NA; k++) {
        int j = c_pathj[a][k];
        P1[k].x = g_m1T[(j * 3 + 0) * F + f];
        P1[k].y = g_m1T[(j * 3 + 1) * F + f];
        P1[k].z = g_m1T[(j * 3 + 2) * F + f];
    }
#pragma unroll
    for (int k = 0; k < NB; k++) {
        int j = c_pathj[b][k];
        P2[k].x = g_m2T[(j * 3 + 0) * F + f];
        P2[k].y = g_m2T[(j * 3 + 1) * F + f];
        P2[k].z = g_m2T[(j * 3 + 2) * F + f];
    }

    float acc = 0.f;
#pragma unroll
    for (int i = 0; i < NA - 1; i++) {
        V3 s1 = P1[i], e1 = P1[i + 1];
        V3 r12 = vsub(e1, s1);
#pragma unroll
        for (int j = 0; j < NB - 1; j++) {
            V3 s2 = P2[j], e2 = P2[j + 1];
            V3 r13 = vsub(s2, s1);
            V3 r14 = vsub(e2, s1);
            V3 r23 = vsub(r13, r12);   // s2 - e1
            V3 r24 = vsub(r14, r12);   // e2 - e1
            V3 r34 = vsub(r14, r13);   // e2 - s2
            V3 f0 = vcrs(r13, r14);
            V3 f1 = vcrs(r14, r24);
            V3 f2 = vcrs(r24, r23);
            V3 f3 = vcrs(r23, r13);
            float r0 = invnorm(f0), r1 = invnorm(f1);
            float r2 = invnorm(f2), r3 = invnorm(f3);
            float t = edge_asin(f0, r0, f1, r1)
                    + edge_asin(f1, r1, f2, r2)
                    + edge_asin(f2, r2, f3, r3)
                    + edge_asin(f3, r3, f0, r0);
            float sg = vdot(vcrs(r34, r12), r13);
            acc += (sg > 0.f) ? t : -t;
        }
    }
    return acc;
}

// ---------------- kernel 3: per-(bin, frame) GLI, masked ----------------
__global__ void __launch_bounds__(256) gli_kernel() {
    int f = blockIdx.x * blockDim.x + threadIdx.x;
    int bin = blockIdx.y;                 // uniform per block -> no divergence
    int a = bin / 5, b = bin % 5;
    int na = c_plen[a], nb = c_plen[b];

    float acc;
    int key = ((na == 5) ? 2 : 0) | ((nb == 5) ? 1 : 0);
    switch (key) {                         // block-uniform branch
        case 0: acc = gli_body<4, 4>(f, a, b); break;
        case 1: acc = gli_body<4, 5>(f, a, b); break;
        case 2: acc = gli_body<5, 4>(f, a, b); break;
        default: acc = gli_body<5, 5>(f, a, b); break;
    }

    // window mask: flag[f] | flag[f-1] | flag[f+1]
    bool m = g_flag[f];
    if (f > 0)     m = m || g_flag[f - 1];
    if (f < F - 1) m = m || g_flag[f + 1];
    g_gli[bin * F + f] = acc * INV4PI * (m ? 1.f : 0.f);
}

// ---------------- kernel 4: max |delta| over bins ----------------
__global__ void vel_kernel(float* __restrict__ out) {
    int t = blockIdx.x * blockDim.x + threadIdx.x;
    if (t >= F - 1) return;
    float best = 0.f;
#pragma unroll
    for (int bin = 0; bin < NBINS; bin++) {
        float d = fabsf(g_gli[bin * F + t + 1] - g_gli[bin * F + t]);
        best = fmaxf(best, d);
    }
    out[t] = best;
}

// ---------------- launcher ----------------
extern "C" void kernel_launch(void* const* d_in, const int* in_sizes, int n_in,
                              void* d_out, int out_size) {
    const float* m1 = (const float*)d_in[0];
    const float* m2 = (const float*)d_in[1];
    float* out = (float*)d_out;

    transpose_kernel<<<dim3(F / 32, 2), 256>>>(m1, m2);
    mask_kernel<<<F / 256, 256>>>();
    gli_kernel<<<dim3(F / 256, NBINS), 256>>>();
    vel_kernel<<<(F + 255) / 256, 256>>>(out);
}

// round 3
// speedup vs baseline: 1.0853x; 1.0853x over previous
#include <cuda_runtime.h>

#define F 16384
#define NJ 22
#define STRIDE (NJ*3)   // 66 floats per frame
#define NBINS 25
#define INV4PI 0.07957747154594767f
#define PIO2 1.5707963267948966f

// ---------------- device scratch (no allocs allowed) ----------------
__device__ float g_m1T[STRIDE * F];   // [j*3+c][frame]
__device__ float g_m2T[STRIDE * F];
__device__ unsigned char g_flag[F];
__device__ float g_gli[F * NBINS];    // [frame][bin]  (bin-contiguous)

__constant__ int c_pathj[5][5] = {
    {2, 5, 8, 11, 0},
    {1, 4, 7, 10, 0},
    {3, 6, 9, 12, 15},
    {14, 17, 19, 21, 0},
    {13, 16, 18, 20, 0}
};
__constant__ int c_plen[5] = {4, 4, 5, 4, 4};

// ---------------- small vec helpers ----------------
struct V3 { float x, y, z; };

__device__ __forceinline__ V3 vsub(V3 a, V3 b) { return {a.x - b.x, a.y - b.y, a.z - b.z}; }
__device__ __forceinline__ V3 vcrs(V3 a, V3 b) {
    return {fmaf(a.y, b.z, -a.z * b.y),
            fmaf(a.z, b.x, -a.x * b.z),
            fmaf(a.x, b.y, -a.y * b.x)};
}
__device__ __forceinline__ float vdot(V3 a, V3 b) {
    return fmaf(a.x, b.x, fmaf(a.y, b.y, a.z * b.z));
}
// _safe_normalize semantics: zero vector -> zero scale (downstream dot -> 0)
__device__ __forceinline__ float invnorm(V3 v) {
    float n2 = vdot(v, v);
    return (n2 > 0.f) ? rsqrtf(n2) : 0.f;
}

// Branch-free asin via Abramowitz-Stegun 4.4.45 (7-term), |abs err| ~ 2e-8.
// asin(d) = sign(d) * (pi/2 - sqrt(1-|d|) * P(|d|)),  |d| <= 1 (pre-clipped).
__device__ __forceinline__ float fast_asin(float d) {
    float ax = fabsf(d);
    float p = fmaf(ax, -0.0012624911f, 0.0066700901f);
    p = fmaf(ax, p, -0.0170881256f);
    p = fmaf(ax, p,  0.0308918810f);
    p = fmaf(ax, p, -0.0501743046f);
    p = fmaf(ax, p,  0.0889789874f);
    p = fmaf(ax, p, -0.2145988016f);
    p = fmaf(ax, p,  1.5707963050f);
    float s = 1.0f - ax;
    float r = (s > 0.f) ? (s * rsqrtf(s)) * p : 0.f;   // sqrt(s)*p via MUFU.RSQ
    return copysignf(PIO2 - r, d);
}

__device__ __forceinline__ float edge_asin(V3 a, float ra, V3 b, float rb) {
    float d = vdot(a, b) * ra * rb;
    d = fminf(1.f, fmaxf(-1.f, d));
    return fast_asin(d);
}

// ---------------- kernel 1: AoS->SoA transpose + window flag ----------------
__global__ void transpose_mask_kernel(const float* __restrict__ m1,
                                      const float* __restrict__ m2) {
    __shared__ float tile1[32 * STRIDE];
    __shared__ float tile2[32 * STRIDE];
    int f0 = blockIdx.x * 32;

    // coalesced read of 32 contiguous frames for both motions
    for (int idx = threadIdx.x; idx < 32 * STRIDE; idx += blockDim.x) {
        tile1[idx] = m1[f0 * STRIDE + idx];
        tile2[idx] = m2[f0 * STRIDE + idx];
    }
    __syncthreads();
    // coalesced SoA write: 32 consecutive frames per (joint,comp) slot
    for (int idx = threadIdx.x; idx < 32 * STRIDE; idx += blockDim.x) {
        int slot = idx >> 5;
        int lane = idx & 31;
        g_m1T[slot * F + f0 + lane] = tile1[lane * STRIDE + slot];
        g_m2T[slot * F + f0 + lane] = tile2[lane * STRIDE + slot];
    }
    // XZ bbox overlap flag for this block's 32 frames (from smem)
    if (threadIdx.x < 32) {
        int lane = threadIdx.x;
        float x1n = 1e30f, x1x = -1e30f, z1n = 1e30f, z1x = -1e30f;
        float x2n = 1e30f, x2x = -1e30f, z2n = 1e30f, z2x = -1e30f;
#pragma unroll
        for (int j = 0; j < NJ; j++) {
            float x1 = tile1[lane * STRIDE + j * 3 + 0];
            float z1 = tile1[lane * STRIDE + j * 3 + 2];
            float x2 = tile2[lane * STRIDE + j * 3 + 0];
            float z2 = tile2[lane * STRIDE + j * 3 + 2];
            x1n = fminf(x1n, x1); x1x = fmaxf(x1x, x1);
            z1n = fminf(z1n, z1); z1x = fmaxf(z1x, z1);
            x2n = fminf(x2n, x2); x2x = fmaxf(x2x, x2);
            z2n = fminf(z2n, z2); z2x = fmaxf(z2x, z2);
        }
        bool ovx = !((x1x < x2n) || (x2x < x1n));
        bool ovz = !((z1x < z2n) || (z2x < z1n));
        g_flag[f0 + lane] = (unsigned char)(ovx && ovz);
    }
}

// ---------------- GLI pair sum (fully unrolled via templates) ----------------
template <int NA, int NB>
__device__ __forceinline__ float gli_body(int f, int a, int b) {
    V3 P1[NA], P2[NB];
#pragma unroll
    for (int k = 0; k < NA; k++) {
        int j = c_pathj[a][k];
        P1[k].x = g_m1T[(j * 3 + 0) * F + f];
        P1[k].y = g_m1T[(j * 3 + 1) * F + f];
        P1[k].z = g_m1T[(j * 3 + 2) * F + f];
    }
#pragma unroll
    for (int k = 0; k < NB; k++) {
        int j = c_pathj[b][k];
        P2[k].x = g_m2T[(j * 3 + 0) * F + f];
        P2[k].y = g_m2T[(j * 3 + 1) * F + f];
        P2[k].z = g_m2T[(j * 3 + 2) * F + f];
    }

    float acc = 0.f;
#pragma unroll
    for (int i = 0; i < NA - 1; i++) {
        V3 s1 = P1[i], e1 = P1[i + 1];
        V3 r12 = vsub(e1, s1);
#pragma unroll
        for (int j = 0; j < NB - 1; j++) {
            V3 s2 = P2[j], e2 = P2[j + 1];
            V3 r13 = vsub(s2, s1);
            V3 r14 = vsub(e2, s1);
            V3 r23 = vsub(r13, r12);   // s2 - e1
            V3 r24 = vsub(r14, r12);   // e2 - e1
            V3 r34 = vsub(r14, r13);   // e2 - s2
            V3 f0 = vcrs(r13, r14);
            V3 f1 = vcrs(r14, r24);
            V3 f2 = vcrs(r24, r23);
            V3 f3 = vcrs(r23, r13);
            float r0 = invnorm(f0), r1 = invnorm(f1);
            float r2 = invnorm(f2), r3 = invnorm(f3);
            float t = edge_asin(f0, r0, f1, r1)
                    + edge_asin(f1, r1, f2, r2)
                    + edge_asin(f2, r2, f3, r3)
                    + edge_asin(f3, r3, f0, r0);
            float sg = vdot(vcrs(r34, r12), r13);
            acc += (sg > 0.f) ? t : -t;
        }
    }
    return acc;
}

// ---------------- kernel 2: per-(bin, frame) GLI, masked ----------------
__global__ void __launch_bounds__(256) gli_kernel() {
    int f = blockIdx.x * blockDim.x + threadIdx.x;
    int bin = blockIdx.y;                 // uniform per block -> no divergence
    int a = bin / 5, b = bin % 5;
    int na = c_plen[a], nb = c_plen[b];

    float acc;
    int key = ((na == 5) ? 2 : 0) | ((nb == 5) ? 1 : 0);
    switch (key) {                         // block-uniform branch
        case 0: acc = gli_body<4, 4>(f, a, b); break;
        case 1: acc = gli_body<4, 5>(f, a, b); break;
        case 2: acc = gli_body<5, 4>(f, a, b); break;
        default: acc = gli_body<5, 5>(f, a, b); break;
    }

    // window mask: flag[f] | flag[f-1] | flag[f+1]
    bool m = g_flag[f];
    if (f > 0)     m = m || g_flag[f - 1];
    if (f < F - 1) m = m || g_flag[f + 1];
    g_gli[f * NBINS + bin] = acc * INV4PI * (m ? 1.f : 0.f);
}

// ---------------- kernel 3: max |delta| over bins (coalesced stream) -------
__global__ void vel_kernel(float* __restrict__ out) {
    int t = blockIdx.x * blockDim.x + threadIdx.x;
    if (t >= F - 1) return;
    float best = 0.f;
    const float* row0 = g_gli + t * NBINS;
#pragma unroll
    for (int bin = 0; bin < NBINS; bin++) {
        float d = fabsf(row0[bin + NBINS] - row0[bin]);
        best = fmaxf(best, d);
    }
    out[t] = best;
}

// ---------------- launcher ----------------
extern "C" void kernel_launch(void* const* d_in, const int* in_sizes, int n_in,
                              void* d_out, int out_size) {
    const float* m1 = (const float*)d_in[0];
    const float* m2 = (const float*)d_in[1];
    float* out = (float*)d_out;

    transpose_mask_kernel<<<F / 32, 256>>>(m1, m2);
    gli_kernel<<<dim3(F / 256, NBINS), 256>>>();
    vel_kernel<<<(F + 63) / 64, 64>>>(out);
}